// round 16
// baseline (speedup 1.0000x reference)
#include <cuda_runtime.h>
#include <cuda_fp16.h>
#include <cstdint>

// Static problem shapes
#define BATCH 8
#define SEQ   2048
#define DIM   768
#define ROWS  (BATCH * SEQ)       // 16384
#define TEMP_INV (1.0f / 0.07f)

// ---------------------------------------------------------------------------
// Device-global scratch (all-half intermediates)
// ---------------------------------------------------------------------------
__device__ __half g_inH  [2 * ROWS * DIM];          // vis | lang (also out_pre scratch)
__device__ __half g_vpH  [ROWS * DIM];
__device__ __half g_lpH  [ROWS * DIM];
__device__ __half g_AmH[(size_t)BATCH * SEQ * SEQ];
__device__ __half g_combH[ROWS * 2 * DIM];          // also proj-GEMM tmp
__device__ __half g_WH  [2 * DIM * DIM];            // vW | lW
__device__ __half g_oWH [2 * DIM * DIM];
__device__ float  g_pb  [2 * DIM];                  // vb | lb
__device__ float  g_part[144];
__device__ float  g_scale;

// ---------------------------------------------------------------------------
// PTX helpers
// ---------------------------------------------------------------------------
__device__ __forceinline__ uint32_t smem_u32(const void* p) {
    uint32_t a;
    asm("{ .reg .u64 t; cvta.to.shared.u64 t, %1; cvt.u32.u64 %0, t; }" : "=r"(a) : "l"(p));
    return a;
}
__device__ __forceinline__ void cp16(void* sdst, const void* gsrc) {
    asm volatile("cp.async.cg.shared.global [%0], [%1], 16;"
                 :: "r"(smem_u32(sdst)), "l"(__cvta_generic_to_global(gsrc)) : "memory");
}
__device__ __forceinline__ void ldsm4(uint32_t* r, uint32_t addr) {
    asm volatile("ldmatrix.sync.aligned.m8n8.x4.shared.b16 {%0,%1,%2,%3}, [%4];"
                 : "=r"(r[0]), "=r"(r[1]), "=r"(r[2]), "=r"(r[3]) : "r"(addr));
}
__device__ __forceinline__ void ldsm4t(uint32_t* r, uint32_t addr) {
    asm volatile("ldmatrix.sync.aligned.m8n8.x4.trans.shared.b16 {%0,%1,%2,%3}, [%4];"
                 : "=r"(r[0]), "=r"(r[1]), "=r"(r[2]), "=r"(r[3]) : "r"(addr));
}
__device__ __forceinline__ void mma16816(float* c, const uint32_t* a, const uint32_t* b) {
    asm volatile(
        "mma.sync.aligned.m16n8k16.row.col.f32.f16.f16.f32 "
        "{%0,%1,%2,%3}, {%4,%5,%6,%7}, {%8,%9}, {%0,%1,%2,%3};"
        : "+f"(c[0]), "+f"(c[1]), "+f"(c[2]), "+f"(c[3])
        : "r"(a[0]), "r"(a[1]), "r"(a[2]), "r"(a[3]), "r"(b[0]), "r"(b[1]));
}
__device__ __forceinline__ void mma16816h(uint32_t* c, const uint32_t* a, const uint32_t* b) {
    asm volatile(
        "mma.sync.aligned.m16n8k16.row.col.f16.f16.f16.f16 "
        "{%0,%1}, {%2,%3,%4,%5}, {%6,%7}, {%0,%1};"
        : "+r"(c[0]), "+r"(c[1])
        : "r"(a[0]), "r"(a[1]), "r"(a[2]), "r"(a[3]), "r"(b[0]), "r"(b[1]));
}
__device__ __forceinline__ void store2(float* p, float x, float y) {
    *reinterpret_cast<float2*>(p) = make_float2(x, y);
}
__device__ __forceinline__ void store2(__half* p, float x, float y) {
    *reinterpret_cast<__half2*>(p) = __floats2half2_rn(x, y);
}

#define SMJ 72    // K64 tiles: [rows][72] halves, 36-word row step, LDSM conflict-free
#define SMS 40    // K32 tiles (sim): [rows][40]

// ---------------------------------------------------------------------------
// fp16 mma.sync GEMM (f32 acc), M-tile 64: C[M,N] = alpha*opA@opB + bias
//   TRA=0: A stored [M,K]; TRA=1: A stored [K,M]
//   TRB=0: B stored [N,K]; TRB=1: B stored [K,N]
// CTA 64x128x64, 8 warps (2x4), warp tile 32x32. 3-stage cp.async, 2 CTA/SM.
// grid = (N/128, M/64, z).
// ---------------------------------------------------------------------------
#define SMKA 72   // A [64][64+8] when TRA=1
#define SMKB 136  // B [64][128+8] when TRB=1

template <int TRA, int TRB>
struct GemmSmem {
    static constexpr int AH = TRA ? 64 * SMKA : 64 * SMJ;   // 4608 both
    static constexpr int BH = TRB ? 64 * SMKB : 128 * SMJ;
    static constexpr int BYTES = 3 * (AH + BH) * 2;
};

template <int TRA, int TRB, typename OUT>
__global__ __launch_bounds__(256, 2)
void h_gemm(const __half* __restrict__ Ag, const __half* __restrict__ Bg,
            OUT* __restrict__ Cg,
            int lda, int ldb, int ldc, int K,
            long long sA, long long sB, long long sC, long long sBias,
            const float* __restrict__ alpha_ptr, const float* __restrict__ bias) {
    constexpr int AH = GemmSmem<TRA, TRB>::AH;
    constexpr int BH = GemmSmem<TRA, TRB>::BH;
    extern __shared__ char dynsm[];
    __half* Asm = reinterpret_cast<__half*>(dynsm);
    __half* Bsm = Asm + 3 * AH;

    const int tid  = threadIdx.x;
    const int wid  = tid >> 5;
    const int lane = tid & 31;
    const int gid  = lane >> 2;
    const int t4   = lane & 3;
    const int warp_m = (wid >> 2) * 32;   // 0 or 32
    const int warp_n = (wid & 3) * 32;

    const __half* A = Ag + (long long)blockIdx.z * sA
                    + (TRA ? (long long)blockIdx.y * 64 : (long long)blockIdx.y * 64 * lda);
    const __half* B = Bg + (long long)blockIdx.z * sB
                    + (TRB ? (long long)blockIdx.x * 128 : (long long)blockIdx.x * 128 * ldb);
    if (bias) bias += (long long)blockIdx.z * sBias;

    const int aoff = TRA
        ? ((lane & 7) + 8 * (lane >> 4)) * SMKA + warp_m + 8 * ((lane >> 3) & 1)
        : (warp_m + (lane & 7) + 8 * ((lane >> 3) & 1)) * SMJ + 8 * (lane >> 4);
    const int boff = TRB
        ? ((lane & 7) + 8 * ((lane >> 3) & 1)) * SMKB + warp_n + 8 * (lane >> 4)
        : (warp_n + (lane & 7) + 8 * (lane >> 4)) * SMJ + 8 * ((lane >> 3) & 1);
    const uint32_t aBase0 = smem_u32(&Asm[aoff]);
    const uint32_t bBase0 = smem_u32(&Bsm[boff]);

    float acc[2][4][4] = {};
    const int KT = K >> 6;

    auto load_stage = [&](int st, int kt) {
        const int k0 = kt * 64;
        __half* As = Asm + st * AH;
        __half* Bs = Bsm + st * BH;
        // A: 512 chunks of 8 halves (64x64)
        #pragma unroll
        for (int i = 0; i < 2; i++) {
            int chunk = tid + i * 256;
            if (TRA == 0) {
                int row = chunk >> 3, c = (chunk & 7) * 8;
                cp16(&As[row * SMJ + c], A + (long long)row * lda + k0 + c);
            } else {
                int row = chunk >> 3, c = (chunk & 7) * 8;
                cp16(&As[row * SMKA + c], A + (long long)(k0 + row) * lda + c);
            }
        }
        // B: 1024 chunks (128x64 or 64x128)
        #pragma unroll
        for (int i = 0; i < 4; i++) {
            int chunk = tid + i * 256;
            if (TRB == 0) {
                int row = chunk >> 3, c = (chunk & 7) * 8;
                cp16(&Bs[row * SMJ + c], B + (long long)row * ldb + k0 + c);
            } else {
                int row = chunk >> 4, c = (chunk & 15) * 8;
                cp16(&Bs[row * SMKB + c], B + (long long)(k0 + row) * ldb + c);
            }
        }
        asm volatile("cp.async.commit_group;" ::: "memory");
    };

    load_stage(0, 0);
    if (KT > 1) load_stage(1, 1);

    int sc = 0, sl = 2;
    for (int kt = 0; kt < KT; kt++) {
        if (kt + 1 < KT) asm volatile("cp.async.wait_group 1;" ::: "memory");
        else             asm volatile("cp.async.wait_group 0;" ::: "memory");
        __syncthreads();

        if (kt + 2 < KT) load_stage(sl, kt + 2);

        const uint32_t aB = aBase0 + sc * AH * 2;
        const uint32_t bB = bBase0 + sc * BH * 2;
        #pragma unroll
        for (int ks = 0; ks < 4; ks++) {
            uint32_t afr[2][4], bfr[4][2], btmp[4];
            #pragma unroll
            for (int mb = 0; mb < 2; mb++) {
                if (TRA) ldsm4t(afr[mb], aB + (ks * 16 * SMKA + mb * 16) * 2);
                else     ldsm4 (afr[mb], aB + (mb * 16 * SMJ + ks * 16) * 2);
            }
            #pragma unroll
            for (int h = 0; h < 2; h++) {
                if (TRB) ldsm4t(btmp, bB + (ks * 16 * SMKB + h * 16) * 2);
                else     ldsm4 (btmp, bB + (h * 16 * SMJ + ks * 16) * 2);
                bfr[2 * h][0]     = btmp[0]; bfr[2 * h][1]     = btmp[1];
                bfr[2 * h + 1][0] = btmp[2]; bfr[2 * h + 1][1] = btmp[3];
            }
            #pragma unroll
            for (int mb = 0; mb < 2; mb++)
                #pragma unroll
                for (int nb = 0; nb < 4; nb++)
                    mma16816(acc[mb][nb], afr[mb], bfr[nb]);
        }
        sc = (sc == 2) ? 0 : sc + 1;
        sl = (sl == 2) ? 0 : sl + 1;
    }

    const float alpha = alpha_ptr ? *alpha_ptr : 1.0f;
    OUT* C = Cg + (long long)blockIdx.z * sC + (long long)blockIdx.y * 64 * ldc
           + (long long)blockIdx.x * 128;
    const int colbase = blockIdx.x * 128;
    #pragma unroll
    for (int mb = 0; mb < 2; mb++) {
        const int row = warp_m + mb * 16 + gid;
        #pragma unroll
        for (int nb = 0; nb < 4; nb++) {
            const int col = warp_n + nb * 8 + 2 * t4;
            float bx = 0.0f, by = 0.0f;
            if (bias) { bx = bias[colbase + col]; by = bias[colbase + col + 1]; }
            store2(&C[(long long)row * ldc + col],
                   acc[mb][nb][0] * alpha + bx, acc[mb][nb][1] * alpha + by);
            store2(&C[(long long)(row + 8) * ldc + col],
                   acc[mb][nb][2] * alpha + bx, acc[mb][nb][3] * alpha + by);
        }
    }
}

// ---------------------------------------------------------------------------
// sim GEMM, f16 acc, M-tile 64: Am[b] = (vp[b] @ lp[b]^T) * scale.
// CTA 64x128x32, 8 warps (2x4), warp tile 32x32. grid (SEQ/128, SEQ/64, BATCH).
// ---------------------------------------------------------------------------
#define SIM_AH (64 * SMS)     // 2560
#define SIM_BH (128 * SMS)    // 5120
#define SIM_BYTES (3 * (SIM_AH + SIM_BH) * 2)   // 46080

__global__ __launch_bounds__(256, 3)
void sim_gemm_h16(const __half* __restrict__ vp, const __half* __restrict__ lp,
                  __half* __restrict__ Am, const float* __restrict__ alpha_ptr) {
    extern __shared__ char dynsm[];
    __half* Asm = reinterpret_cast<__half*>(dynsm);
    __half* Bsm = Asm + 3 * SIM_AH;

    const int tid  = threadIdx.x;
    const int wid  = tid >> 5;
    const int lane = tid & 31;
    const int gid  = lane >> 2;
    const int t4   = lane & 3;
    const int warp_m = (wid >> 2) * 32;    // 0,32
    const int warp_n = (wid & 3) * 32;     // 0,32,64,96

    const long long SD = (long long)SEQ * DIM;
    const __half* A = vp + (long long)blockIdx.z * SD + (long long)blockIdx.y * 64 * DIM;
    const __half* B = lp + (long long)blockIdx.z * SD + (long long)blockIdx.x * 128 * DIM;

    const int aoff = (warp_m + (lane & 7) + 8 * ((lane >> 3) & 1)) * SMS + 8 * (lane >> 4);
    const int boff = (warp_n + (lane & 7) + 8 * (lane >> 4)) * SMS + 8 * ((lane >> 3) & 1);
    const uint32_t aBase0 = smem_u32(&Asm[aoff]);
    const uint32_t bBase0 = smem_u32(&Bsm[boff]);

    uint32_t acc[2][4][2] = {};    // f16x2 accumulators (16 regs)
    const int KT = DIM >> 5;       // 24

    auto load_stage = [&](int st, int kt) {
        const int k0 = kt * 32;
        __half* As = Asm + st * SIM_AH;
        __half* Bs = Bsm + st * SIM_BH;
        {   // A: 256 chunks (64 rows x 4 chunks)
            int chunk = tid;
            int row = chunk >> 2, c = (chunk & 3) * 8;
            cp16(&As[row * SMS + c], A + (long long)row * DIM + k0 + c);
        }
        #pragma unroll
        for (int i = 0; i < 2; i++) {   // B: 512 chunks
            int chunk = tid + i * 256;
            int row = chunk >> 2, c = (chunk & 3) * 8;
            cp16(&Bs[row * SMS + c], B + (long long)row * DIM + k0 + c);
        }
        asm volatile("cp.async.commit_group;" ::: "memory");
    };

    load_stage(0, 0);
    load_stage(1, 1);

    int sc = 0, sl = 2;
    for (int kt = 0; kt < KT; kt++) {
        if (kt + 1 < KT) asm volatile("cp.async.wait_group 1;" ::: "memory");
        else             asm volatile("cp.async.wait_group 0;" ::: "memory");
        __syncthreads();

        if (kt + 2 < KT) load_stage(sl, kt + 2);

        const uint32_t aB = aBase0 + sc * SIM_AH * 2;
        const uint32_t bB = bBase0 + sc * SIM_BH * 2;
        #pragma unroll
        for (int ks = 0; ks < 2; ks++) {
            uint32_t afr[2][4], bfr[4][2], btmp[4];
            #pragma unroll
            for (int mb = 0; mb < 2; mb++)
                ldsm4(afr[mb], aB + (mb * 16 * SMS + ks * 16) * 2);
            #pragma unroll
            for (int h = 0; h < 2; h++) {
                ldsm4(btmp, bB + (h * 16 * SMS + ks * 16) * 2);
                bfr[2 * h][0]     = btmp[0]; bfr[2 * h][1]     = btmp[1];
                bfr[2 * h + 1][0] = btmp[2]; bfr[2 * h + 1][1] = btmp[3];
            }
            #pragma unroll
            for (int mb = 0; mb < 2; mb++)
                #pragma unroll
                for (int nb = 0; nb < 4; nb++)
                    mma16816h(acc[mb][nb], afr[mb], bfr[nb]);
        }
        sc = (sc == 2) ? 0 : sc + 1;
        sl = (sl == 2) ? 0 : sl + 1;
    }

    const float alpha = *alpha_ptr;
    __half* C = Am + (long long)blockIdx.z * SEQ * SEQ
              + (long long)blockIdx.y * 64 * SEQ + (long long)blockIdx.x * 128;
    #pragma unroll
    for (int mb = 0; mb < 2; mb++) {
        const int row = warp_m + mb * 16 + gid;
        #pragma unroll
        for (int nb = 0; nb < 4; nb++) {
            const int col = warp_n + nb * 8 + 2 * t4;
            float2 v0 = __half22float2(*reinterpret_cast<__half2*>(&acc[mb][nb][0]));
            float2 v1 = __half22float2(*reinterpret_cast<__half2*>(&acc[mb][nb][1]));
            store2(&C[(long long)row * SEQ + col], v0.x * alpha, v0.y * alpha);
            store2(&C[(long long)(row + 8) * SEQ + col], v1.x * alpha, v1.y * alpha);
        }
    }
}

// ---------------------------------------------------------------------------
// Merged aligned GEMM, M-tile 64:
//   role 0: comb[:,:768] = A @ vp ; role 1: comb[:,768:] = A^T @ lp
// gridDim = (DIM/128, SEQ/64, 2*BATCH); role = z&1, bat = z>>1. B [K,N] both ways.
// ---------------------------------------------------------------------------
#define ADG_AH (64 * SMJ)     // 4608 (= 64*SMKA too)
#define ADG_BH (64 * SMKB)    // 8704
#define ADG_BYTES (3 * (ADG_AH + ADG_BH) * 2)

__global__ __launch_bounds__(256, 2)
void aligned_dual_gemm(const __half* __restrict__ Amg, const __half* __restrict__ vp,
                       const __half* __restrict__ lp, __half* __restrict__ comb) {
    extern __shared__ char dynsm[];
    __half* Asm = reinterpret_cast<__half*>(dynsm);
    __half* Bsm = Asm + 3 * ADG_AH;

    const int tid  = threadIdx.x;
    const int wid  = tid >> 5;
    const int lane = tid & 31;
    const int gid  = lane >> 2;
    const int t4   = lane & 3;
    const int warp_m = (wid >> 2) * 32;
    const int warp_n = (wid & 3) * 32;

    const int role = blockIdx.z & 1;
    const int bat  = blockIdx.z >> 1;
    const long long SS = (long long)SEQ * SEQ;
    const long long SD = (long long)SEQ * DIM;

    const __half* A = Amg + (long long)bat * SS
                    + (role ? (long long)blockIdx.y * 64
                            : (long long)blockIdx.y * 64 * SEQ);
    const __half* B = (role ? lp : vp) + (long long)bat * SD + (long long)blockIdx.x * 128;

    const int aoff = role
        ? ((lane & 7) + 8 * (lane >> 4)) * SMKA + warp_m + 8 * ((lane >> 3) & 1)
        : (warp_m + (lane & 7) + 8 * ((lane >> 3) & 1)) * SMJ + 8 * (lane >> 4);
    const int boff = ((lane & 7) + 8 * ((lane >> 3) & 1)) * SMKB + warp_n + 8 * (lane >> 4);
    const uint32_t aBase0 = smem_u32(&Asm[aoff]);
    const uint32_t bBase0 = smem_u32(&Bsm[boff]);

    float acc[2][4][4] = {};
    const int KT = SEQ >> 6;

    auto load_stage = [&](int st, int kt) {
        const int k0 = kt * 64;
        __half* As = Asm + st * ADG_AH;
        __half* Bs = Bsm + st * ADG_BH;
        // A: 512 chunks (64x64)
        #pragma unroll
        for (int i = 0; i < 2; i++) {
            int chunk = tid + i * 256;
            int row = chunk >> 3, c = (chunk & 7) * 8;
            if (role == 0) cp16(&As[row * SMJ + c], A + (long long)row * SEQ + k0 + c);
            else           cp16(&As[row * SMKA + c], A + (long long)(k0 + row) * SEQ + c);
        }
        // B: 1024 chunks (64x128)
        #pragma unroll
        for (int i = 0; i < 4; i++) {
            int chunk = tid + i * 256;
            int row = chunk >> 4, c = (chunk & 15) * 8;
            cp16(&Bs[row * SMKB + c], B + (long long)(k0 + row) * DIM + c);
        }
        asm volatile("cp.async.commit_group;" ::: "memory");
    };

    load_stage(0, 0);
    load_stage(1, 1);

    int sc = 0, sl = 2;
    for (int kt = 0; kt < KT; kt++) {
        if (kt + 1 < KT) asm volatile("cp.async.wait_group 1;" ::: "memory");
        else             asm volatile("cp.async.wait_group 0;" ::: "memory");
        __syncthreads();

        if (kt + 2 < KT) load_stage(sl, kt + 2);

        const uint32_t aB = aBase0 + sc * ADG_AH * 2;
        const uint32_t bB = bBase0 + sc * ADG_BH * 2;
        #pragma unroll
        for (int ks = 0; ks < 4; ks++) {
            uint32_t afr[2][4], bfr[4][2], btmp[4];
            #pragma unroll
            for (int mb = 0; mb < 2; mb++) {
                if (role) ldsm4t(afr[mb], aB + (ks * 16 * SMKA + mb * 16) * 2);
                else      ldsm4 (afr[mb], aB + (mb * 16 * SMJ + ks * 16) * 2);
            }
            #pragma unroll
            for (int h = 0; h < 2; h++) {
                ldsm4t(btmp, bB + (ks * 16 * SMKB + h * 16) * 2);
                bfr[2 * h][0]     = btmp[0]; bfr[2 * h][1]     = btmp[1];
                bfr[2 * h + 1][0] = btmp[2]; bfr[2 * h + 1][1] = btmp[3];
            }
            #pragma unroll
            for (int mb = 0; mb < 2; mb++)
                #pragma unroll
                for (int nb = 0; nb < 4; nb++)
                    mma16816(acc[mb][nb], afr[mb], bfr[nb]);
        }
        sc = (sc == 2) ? 0 : sc + 1;
        sl = (sl == 2) ? 0 : sl + 1;
    }

    __half* C = comb + (long long)bat * SEQ * 2 * DIM + role * DIM
              + (long long)blockIdx.y * 64 * (2 * DIM) + (long long)blockIdx.x * 128;
    #pragma unroll
    for (int mb = 0; mb < 2; mb++) {
        const int row = warp_m + mb * 16 + gid;
        #pragma unroll
        for (int nb = 0; nb < 4; nb++) {
            const int col = warp_n + nb * 8 + 2 * t4;
            store2(&C[(long long)row * (2 * DIM) + col], acc[mb][nb][0], acc[mb][nb][1]);
            store2(&C[(long long)(row + 8) * (2 * DIM) + col], acc[mb][nb][2], acc[mb][nb][3]);
        }
    }
}

// ---------------------------------------------------------------------------
// Reductions
// ---------------------------------------------------------------------------
__device__ __forceinline__ float blk_sum256(float v, float* ws, int tid) {
    #pragma unroll
    for (int o = 16; o > 0; o >>= 1) v += __shfl_xor_sync(0xFFFFFFFFu, v, o);
    if ((tid & 31) == 0) ws[tid >> 5] = v;
    __syncthreads();
    float t = ws[0];
    #pragma unroll
    for (int i = 1; i < 8; i++) t += ws[i];
    return t;
}

// ---------------------------------------------------------------------------
// Merged prep: claw partials | bias pack | weight f2h | input f2h
// ---------------------------------------------------------------------------
#define W4 (DIM * DIM / 4)
#define N4 (ROWS * DIM / 4)
#define PREP_BLOCKS (144 + 1 + (4 * W4 / 256) + (2 * N4 / 256))

__device__ __forceinline__ void f2h_quad(const float* in, __half* out, int j) {
    float4 v = reinterpret_cast<const float4*>(in)[j];
    __half2* o = reinterpret_cast<__half2*>(out);
    o[2 * j]     = __floats2half2_rn(v.x, v.y);
    o[2 * j + 1] = __floats2half2_rn(v.z, v.w);
}

__global__ void prep_kernel(const float* __restrict__ claw,
                            const float* __restrict__ vb, const float* __restrict__ lb,
                            const float* __restrict__ vW, const float* __restrict__ lW,
                            const float* __restrict__ oW,
                            const float* __restrict__ vis, const float* __restrict__ lang) {
    __shared__ float ws[8];
    const int bx = blockIdx.x, tid = threadIdx.x;
    if (bx < 144) {
        const float* p = claw + (long long)bx * 4096;
        float s = 0.0f;
        #pragma unroll
        for (int i = 0; i < 4; i++) {
            float4 v = reinterpret_cast<const float4*>(p)[tid + i * 256];
            s += v.x + v.y + v.z + v.w;
        }
        s = blk_sum256(s, ws, tid);
        if (tid == 0) g_part[bx] = s;
    } else if (bx == 144) {
        #pragma unroll
        for (int i = 0; i < 6; i++) {
            int j = tid + i * 256;
            g_pb[j] = (j < DIM) ? vb[j] : lb[j - DIM];
        }
    } else if (bx < 145 + 4 * W4 / 256) {
        int j = (bx - 145) * 256 + tid;
        if (j < W4)            f2h_quad(vW, g_WH, j);
        else if (j < 2 * W4)   f2h_quad(lW, g_WH + DIM * DIM, j - W4);
        else                   f2h_quad(oW, g_oWH, j - 2 * W4);
    } else {
        int j = (bx - (145 + 4 * W4 / 256)) * 256 + tid;
        if (j < N4) f2h_quad(vis, g_inH, j);
        else        f2h_quad(lang, g_inH + (long long)ROWS * DIM, j - N4);
    }
}

// ---------------------------------------------------------------------------
// Warp-per-row LayerNorm (+ReLU): 8 rows per 256-thread block.
// ---------------------------------------------------------------------------
__device__ __forceinline__ void ln_warp_row_h(const __half* __restrict__ xrow,
                                              __half* __restrict__ yrow,
                                              const float* __restrict__ g,
                                              const float* __restrict__ beta, int lane) {
    const int4* xv = reinterpret_cast<const int4*>(xrow);
    int4 raw[3];
    float v[24];
    #pragma unroll
    for (int i = 0; i < 3; i++) raw[i] = xv[lane + 32 * i];
    #pragma unroll
    for (int i = 0; i < 3; i++) {
        const __half2* h = reinterpret_cast<const __half2*>(&raw[i]);
        #pragma unroll
        for (int j = 0; j < 4; j++) {
            float2 f = __half22float2(h[j]);
            v[i * 8 + 2 * j] = f.x; v[i * 8 + 2 * j + 1] = f.y;
        }
    }
    float s = 0.0f, s2 = 0.0f;
    #pragma unroll
    for (int k = 0; k < 24; k++) { s += v[k]; s2 += v[k] * v[k]; }
    #pragma unroll
    for (int o = 16; o > 0; o >>= 1) {
        s  += __shfl_xor_sync(0xFFFFFFFFu, s,  o);
        s2 += __shfl_xor_sync(0xFFFFFFFFu, s2, o);
    }
    const float m  = s * (1.0f / DIM);
    const float rs = rsqrtf(s2 * (1.0f / DIM) - m * m + 1e-5f);
    const float4* g4 = reinterpret_cast<const float4*>(g);
    const float4* b4 = reinterpret_cast<const float4*>(beta);
    int4* yv = reinterpret_cast<int4*>(yrow);
    #pragma unroll
    for (int i = 0; i < 3; i++) {
        int ci = (lane + 32 * i) * 2;
        float4 G0 = g4[ci], G1 = g4[ci + 1], B0 = b4[ci], B1 = b4[ci + 1];
        int4 o;
        __half2* oh = reinterpret_cast<__half2*>(&o);
        oh[0] = __floats2half2_rn(fmaxf(0.0f, (v[i*8+0]-m)*rs*G0.x + B0.x),
                                  fmaxf(0.0f, (v[i*8+1]-m)*rs*G0.y + B0.y));
        oh[1] = __floats2half2_rn(fmaxf(0.0f, (v[i*8+2]-m)*rs*G0.z + B0.z),
                                  fmaxf(0.0f, (v[i*8+3]-m)*rs*G0.w + B0.w));
        oh[2] = __floats2half2_rn(fmaxf(0.0f, (v[i*8+4]-m)*rs*G1.x + B1.x),
                                  fmaxf(0.0f, (v[i*8+5]-m)*rs*G1.y + B1.y));
        oh[3] = __floats2half2_rn(fmaxf(0.0f, (v[i*8+6]-m)*rs*G1.z + B1.z),
                                  fmaxf(0.0f, (v[i*8+7]-m)*rs*G1.w + B1.w));
        yv[lane + 32 * i] = o;
    }
}

__device__ __forceinline__ void ln_warp_row_f(const __half* __restrict__ xrow,
                                              float* __restrict__ yrow,
                                              const float* __restrict__ g,
                                              const float* __restrict__ beta, int lane) {
    const int4* xv = reinterpret_cast<const int4*>(xrow);
    int4 raw[3];
    float v[24];
    #pragma unroll
    for (int i = 0; i < 3; i++) raw[i] = xv[lane + 32 * i];
    #pragma unroll
    for (int i = 0; i < 3; i++) {
        const __half2* h = reinterpret_cast<const __half2*>(&raw[i]);
        #pragma unroll
        for (int j = 0; j < 4; j++) {
            float2 f = __half22float2(h[j]);
            v[i * 8 + 2 * j] = f.x; v[i * 8 + 2 * j + 1] = f.y;
        }
    }
    float s = 0.0f, s2 = 0.0f;
    #pragma unroll
    for (int k = 0; k < 24; k++) { s += v[k]; s2 += v[k] * v[k]; }
    #pragma unroll
    for (int o = 16; o > 0; o >>= 1) {
        s  += __shfl_xor_sync(0xFFFFFFFFu, s,  o);
        s2 += __shfl_xor_sync(0xFFFFFFFFu, s2, o);
    }
    const float m  = s * (1.0f / DIM);
    const float rs = rsqrtf(s2 * (1.0f / DIM) - m * m + 1e-5f);
    const float4* g4 = reinterpret_cast<const float4*>(g);
    const float4* b4 = reinterpret_cast<const float4*>(beta);
    float4* yv = reinterpret_cast<float4*>(yrow);
    #pragma unroll
    for (int i = 0; i < 3; i++) {
        int ci = (lane + 32 * i) * 2;
        float4 G0 = g4[ci], G1 = g4[ci + 1], B0 = b4[ci], B1 = b4[ci + 1];
        float4 o0, o1;
        o0.x = fmaxf(0.0f, (v[i*8+0]-m)*rs*G0.x + B0.x);
        o0.y = fmaxf(0.0f, (v[i*8+1]-m)*rs*G0.y + B0.y);
        o0.z = fmaxf(0.0f, (v[i*8+2]-m)*rs*G0.z + B0.z);
        o0.w = fmaxf(0.0f, (v[i*8+3]-m)*rs*G0.w + B0.w);
        o1.x = fmaxf(0.0f, (v[i*8+4]-m)*rs*G1.x + B1.x);
        o1.y = fmaxf(0.0f, (v[i*8+5]-m)*rs*G1.y + B1.y);
        o1.z = fmaxf(0.0f, (v[i*8+6]-m)*rs*G1.z + B1.z);
        o1.w = fmaxf(0.0f, (v[i*8+7]-m)*rs*G1.w + B1.w);
        yv[ci]     = o0;
        yv[ci + 1] = o1;
    }
}

#define LN_DUAL_BLOCKS (2 * ROWS / 8 + 1)
__global__ void ln_relu_dual_kernel(const __half* __restrict__ X0, __half* __restrict__ Y0,
                                    const float* __restrict__ g0, const float* __restrict__ b0,
                                    const __half* __restrict__ X1, __half* __restrict__ Y1,
                                    const float* __restrict__ g1, const float* __restrict__ b1) {
    if (blockIdx.x == LN_DUAL_BLOCKS - 1) {
        __shared__ float ws[8];
        float s = (threadIdx.x < 144) ? g_part[threadIdx.x] : 0.0f;
        s = blk_sum256(s, ws, threadIdx.x);
        if (threadIdx.x == 0) g_scale = (s / (float)(DIM * DIM)) * TEMP_INV;
        return;
    }
    const int lane = threadIdx.x & 31;
    long long r = (long long)blockIdx.x * 8 + (threadIdx.x >> 5);
    if (r < ROWS) ln_warp_row_h(X0 + r * DIM, Y0 + r * DIM, g0, b0, lane);
    else {
        r -= ROWS;
        ln_warp_row_h(X1 + r * DIM, Y1 + r * DIM, g1, b1, lane);
    }
}

__global__ void ln_relu_f_kernel(const __half* __restrict__ X, float* __restrict__ Y,
                                 const float* __restrict__ g, const float* __restrict__ beta) {
    const int lane = threadIdx.x & 31;
    long long r = (long long)blockIdx.x * 8 + (threadIdx.x >> 5);
    ln_warp_row_f(X + r * DIM, Y + r * DIM, g, beta, lane);
}

// ---------------------------------------------------------------------------
// Warp-per-row softmax over 2048, half, in place. 8 rows per block, 64 vals/lane.
// ---------------------------------------------------------------------------
__global__ void softmax_h_kernel(__half* __restrict__ X) {
    const int lane = threadIdx.x & 31;
    long long r = (long long)blockIdx.x * 8 + (threadIdx.x >> 5);
    int4* xv = reinterpret_cast<int4*>(X + r * SEQ);

    int4 raw[8];
    float v[64];
    #pragma unroll
    for (int i = 0; i < 8; i++) raw[i] = xv[lane + 32 * i];
    #pragma unroll
    for (int i = 0; i < 8; i++) {
        const __half2* h = reinterpret_cast<const __half2*>(&raw[i]);
        #pragma unroll
        for (int j = 0; j < 4; j++) {
            float2 f = __half22float2(h[j]);
            v[i * 8 + 2 * j] = f.x; v[i * 8 + 2 * j + 1] = f.y;
        }
    }
    float mx = v[0];
    #pragma unroll
    for (int k = 1; k < 64; k++) mx = fmaxf(mx, v[k]);
    #pragma unroll
    for (int o = 16; o > 0; o >>= 1) mx = fmaxf(mx, __shfl_xor_sync(0xFFFFFFFFu, mx, o));

    float sum = 0.0f;
    #pragma unroll
    for (int k = 0; k < 64; k++) { v[k] = __expf(v[k] - mx); sum += v[k]; }
    #pragma unroll
    for (int o = 16; o > 0; o >>= 1) sum += __shfl_xor_sync(0xFFFFFFFFu, sum, o);
    const float inv = 1.0f / sum;

    #pragma unroll
    for (int i = 0; i < 8; i++) {
        int4 o;
        __half2* oh = reinterpret_cast<__half2*>(&o);
        #pragma unroll
        for (int j = 0; j < 4; j++)
            oh[j] = __floats2half2_rn(v[i * 8 + 2 * j] * inv, v[i * 8 + 2 * j + 1] * inv);
        xv[lane + 32 * i] = o;
    }
}

// ---------------------------------------------------------------------------
// Launch
// ---------------------------------------------------------------------------
extern "C" void kernel_launch(void* const* d_in, const int* in_sizes, int n_in,
                              void* d_out, int out_size) {
    const float* vis   = (const float*)d_in[0];
    const float* lang  = (const float*)d_in[1];
    const float* vW    = (const float*)d_in[2];
    const float* vb    = (const float*)d_in[3];
    const float* vg    = (const float*)d_in[4];
    const float* vbeta = (const float*)d_in[5];
    const float* lW    = (const float*)d_in[6];
    const float* lb    = (const float*)d_in[7];
    const float* lg    = (const float*)d_in[8];
    const float* lbeta = (const float*)d_in[9];
    const float* claw  = (const float*)d_in[10];
    const float* oW    = (const float*)d_in[11];
    const float* ob    = (const float*)d_in[12];
    const float* og    = (const float*)d_in[13];
    const float* obeta = (const float*)d_in[14];
    float* out = (float*)d_out;

    float  *scale, *pb;
    __half *inH, *vpH, *lpH, *AmH, *combH, *WH, *oWH;
    cudaGetSymbolAddress((void**)&inH,   g_inH);
    cudaGetSymbolAddress((void**)&vpH,   g_vpH);
    cudaGetSymbolAddress((void**)&lpH,   g_lpH);
    cudaGetSymbolAddress((void**)&AmH,   g_AmH);
    cudaGetSymbolAddress((void**)&combH, g_combH);
    cudaGetSymbolAddress((void**)&WH,    g_WH);
    cudaGetSymbolAddress((void**)&oWH,   g_oWH);
    cudaGetSymbolAddress((void**)&scale, g_scale);
    cudaGetSymbolAddress((void**)&pb,    g_pb);

    __half* tmpH0 = combH;
    __half* outH  = inH;

    const long long RD = (long long)ROWS * DIM;

    constexpr int SM01 = GemmSmem<0, 1>::BYTES;
    cudaFuncSetAttribute(h_gemm<0, 1, __half>, cudaFuncAttributeMaxDynamicSharedMemorySize, SM01);
    cudaFuncSetAttribute(sim_gemm_h16, cudaFuncAttributeMaxDynamicSharedMemorySize, SIM_BYTES);
    cudaFuncSetAttribute(aligned_dual_gemm, cudaFuncAttributeMaxDynamicSharedMemorySize, ADG_BYTES);

    prep_kernel<<<PREP_BLOCKS, 256>>>(claw, vb, lb, vW, lW, oW, vis, lang);

    // dual proj GEMM: z=0 vis/vW/vb, z=1 lang/lW/lb  (M tiles of 64)
    h_gemm<0, 1, __half><<<dim3(DIM / 128, ROWS / 64, 2), 256, SM01>>>(
        inH, WH, tmpH0, DIM, DIM, DIM, DIM,
        RD, (long long)DIM * DIM, RD, DIM, nullptr, pb);

    // dual LN + ReLU -> vpH, lpH (warp per row) + claw finalize
    ln_relu_dual_kernel<<<LN_DUAL_BLOCKS, 256>>>(tmpH0, vpH, vg, vbeta,
                                                 tmpH0 + RD, lpH, lg, lbeta);

    // sim = (vp @ lp^T) * scale -> half (f16 acc, M tiles of 64)
    sim_gemm_h16<<<dim3(SEQ / 128, SEQ / 64, BATCH), 256, SIM_BYTES>>>(
        vpH, lpH, AmH, scale);

    softmax_h_kernel<<<BATCH * SEQ / 8, 256>>>(AmH);

    // merged aligned GEMMs (M tiles of 64)
    aligned_dual_gemm<<<dim3(DIM / 128, SEQ / 64, 2 * BATCH), 256, ADG_BYTES>>>(
        AmH, vpH, lpH, combH);

    // out_pre = comb @ oW + ob -> half (inH scratch)
    h_gemm<0, 1, __half><<<dim3(DIM / 128, ROWS / 64, 1), 256, SM01>>>(
        combH, oWH, outH, 2 * DIM, DIM, DIM, 2 * DIM, 0, 0, 0, 0, nullptr, ob);

    // final LN + ReLU -> f32 out (warp per row)
    ln_relu_f_kernel<<<ROWS / 8, 256>>>(outH, out, og, obeta);
}

// round 17
// speedup vs baseline: 1.1567x; 1.1567x over previous
#include <cuda_runtime.h>
#include <cuda_fp16.h>
#include <cstdint>

// Static problem shapes
#define BATCH 8
#define SEQ   2048
#define DIM   768
#define ROWS  (BATCH * SEQ)       // 16384
#define TEMP_INV (1.0f / 0.07f)

// ---------------------------------------------------------------------------
// Device-global scratch (all-half intermediates)
// ---------------------------------------------------------------------------
__device__ __half g_inH  [2 * ROWS * DIM];          // vis | lang (also out_pre scratch)
__device__ __half g_vpH  [ROWS * DIM];
__device__ __half g_lpH  [ROWS * DIM];
__device__ __half g_AmH[(size_t)BATCH * SEQ * SEQ];
__device__ __half g_combH[ROWS * 2 * DIM];          // also proj-GEMM tmp
__device__ __half g_WH  [2 * DIM * DIM];            // vW | lW
__device__ __half g_oWH [2 * DIM * DIM];
__device__ float  g_pb  [2 * DIM];                  // vb | lb
__device__ float  g_part[144];
__device__ float  g_scale;

// ---------------------------------------------------------------------------
// PTX helpers
// ---------------------------------------------------------------------------
__device__ __forceinline__ uint32_t smem_u32(const void* p) {
    uint32_t a;
    asm("{ .reg .u64 t; cvta.to.shared.u64 t, %1; cvt.u32.u64 %0, t; }" : "=r"(a) : "l"(p));
    return a;
}
__device__ __forceinline__ void cp16(void* sdst, const void* gsrc) {
    asm volatile("cp.async.cg.shared.global [%0], [%1], 16;"
                 :: "r"(smem_u32(sdst)), "l"(__cvta_generic_to_global(gsrc)) : "memory");
}
__device__ __forceinline__ void ldsm4(uint32_t* r, uint32_t addr) {
    asm volatile("ldmatrix.sync.aligned.m8n8.x4.shared.b16 {%0,%1,%2,%3}, [%4];"
                 : "=r"(r[0]), "=r"(r[1]), "=r"(r[2]), "=r"(r[3]) : "r"(addr));
}
__device__ __forceinline__ void ldsm4t(uint32_t* r, uint32_t addr) {
    asm volatile("ldmatrix.sync.aligned.m8n8.x4.trans.shared.b16 {%0,%1,%2,%3}, [%4];"
                 : "=r"(r[0]), "=r"(r[1]), "=r"(r[2]), "=r"(r[3]) : "r"(addr));
}
__device__ __forceinline__ void mma16816(float* c, const uint32_t* a, const uint32_t* b) {
    asm volatile(
        "mma.sync.aligned.m16n8k16.row.col.f32.f16.f16.f32 "
        "{%0,%1,%2,%3}, {%4,%5,%6,%7}, {%8,%9}, {%0,%1,%2,%3};"
        : "+f"(c[0]), "+f"(c[1]), "+f"(c[2]), "+f"(c[3])
        : "r"(a[0]), "r"(a[1]), "r"(a[2]), "r"(a[3]), "r"(b[0]), "r"(b[1]));
}
// f16-accumulator variant: c = {half2, half2} covering rows (g, g+8)
__device__ __forceinline__ void mma16816h(uint32_t* c, const uint32_t* a, const uint32_t* b) {
    asm volatile(
        "mma.sync.aligned.m16n8k16.row.col.f16.f16.f16.f16 "
        "{%0,%1}, {%2,%3,%4,%5}, {%6,%7}, {%0,%1};"
        : "+r"(c[0]), "+r"(c[1])
        : "r"(a[0]), "r"(a[1]), "r"(a[2]), "r"(a[3]), "r"(b[0]), "r"(b[1]));
}
__device__ __forceinline__ void store2(float* p, float x, float y) {
    *reinterpret_cast<float2*>(p) = make_float2(x, y);
}
__device__ __forceinline__ void store2(__half* p, float x, float y) {
    *reinterpret_cast<__half2*>(p) = __floats2half2_rn(x, y);
}

#define SMJ 72    // [128][72] halves: LDSM conflict-free (K64 tiles)
#define SMK 136   // [64][136] halves: conflict-free
#define SMS 40    // [rows][40] halves: K32 tiles (sim kernel)

// ---------------------------------------------------------------------------
// fp16 mma.sync GEMM (f32 acc): C[M,N] = alpha * opA @ opB + bias
// CTA 128x128x64, 8 warps (2x4), warp tile 64x32. 3-stage cp.async, 2 CTA/SM.
// ---------------------------------------------------------------------------
template <int TRA, int TRB>
struct GemmSmem {
    static constexpr int AH = TRA ? 64 * SMK : 128 * SMJ;
    static constexpr int BH = TRB ? 64 * SMK : 128 * SMJ;
    static constexpr int BYTES = 3 * (AH + BH) * 2;
};

template <int TRA, int TRB, typename OUT>
__global__ __launch_bounds__(256, 2)
void h_gemm(const __half* __restrict__ Ag, const __half* __restrict__ Bg,
            OUT* __restrict__ Cg,
            int lda, int ldb, int ldc, int K,
            long long sA, long long sB, long long sC, long long sBias,
            const float* __restrict__ alpha_ptr, const float* __restrict__ bias) {
    constexpr int AH = GemmSmem<TRA, TRB>::AH;
    constexpr int BH = GemmSmem<TRA, TRB>::BH;
    extern __shared__ char dynsm[];
    __half* Asm = reinterpret_cast<__half*>(dynsm);
    __half* Bsm = Asm + 3 * AH;

    const int tid  = threadIdx.x;
    const int wid  = tid >> 5;
    const int lane = tid & 31;
    const int gid  = lane >> 2;
    const int t4   = lane & 3;
    const int warp_m = (wid >> 2) * 64;
    const int warp_n = (wid & 3) * 32;

    const __half* A = Ag + (long long)blockIdx.z * sA
                    + (TRA ? (long long)blockIdx.y * 128 : (long long)blockIdx.y * 128 * lda);
    const __half* B = Bg + (long long)blockIdx.z * sB
                    + (TRB ? (long long)blockIdx.x * 128 : (long long)blockIdx.x * 128 * ldb);
    if (bias) bias += (long long)blockIdx.z * sBias;

    const int aoff = TRA
        ? ((lane & 7) + 8 * (lane >> 4)) * SMK + warp_m + 8 * ((lane >> 3) & 1)
        : (warp_m + (lane & 7) + 8 * ((lane >> 3) & 1)) * SMJ + 8 * (lane >> 4);
    const int boff = TRB
        ? ((lane & 7) + 8 * ((lane >> 3) & 1)) * SMK + warp_n + 8 * (lane >> 4)
        : (warp_n + (lane & 7) + 8 * (lane >> 4)) * SMJ + 8 * ((lane >> 3) & 1);
    const uint32_t aBase0 = smem_u32(&Asm[aoff]);
    const uint32_t bBase0 = smem_u32(&Bsm[boff]);

    float acc[4][4][4] = {};
    const int KT = K >> 6;

    auto load_stage = [&](int st, int kt) {
        const int k0 = kt * 64;
        __half* As = Asm + st * AH;
        __half* Bs = Bsm + st * BH;
        #pragma unroll
        for (int i = 0; i < 4; i++) {
            int chunk = tid + i * 256;
            if (TRA == 0) {
                int row = chunk >> 3, c = (chunk & 7) * 8;
                cp16(&As[row * SMJ + c], A + (long long)row * lda + k0 + c);
            } else {
                int row = chunk >> 4, c = (chunk & 15) * 8;
                cp16(&As[row * SMK + c], A + (long long)(k0 + row) * lda + c);
            }
            if (TRB == 0) {
                int row = chunk >> 3, c = (chunk & 7) * 8;
                cp16(&Bs[row * SMJ + c], B + (long long)row * ldb + k0 + c);
            } else {
                int row = chunk >> 4, c = (chunk & 15) * 8;
                cp16(&Bs[row * SMK + c], B + (long long)(k0 + row) * ldb + c);
            }
        }
        asm volatile("cp.async.commit_group;" ::: "memory");
    };

    load_stage(0, 0);
    if (KT > 1) load_stage(1, 1);

    int sc = 0, sl = 2;
    for (int kt = 0; kt < KT; kt++) {
        if (kt + 1 < KT) asm volatile("cp.async.wait_group 1;" ::: "memory");
        else             asm volatile("cp.async.wait_group 0;" ::: "memory");
        __syncthreads();

        if (kt + 2 < KT) load_stage(sl, kt + 2);

        const uint32_t aB = aBase0 + sc * AH * 2;
        const uint32_t bB = bBase0 + sc * BH * 2;
        #pragma unroll
        for (int ks = 0; ks < 4; ks++) {
            uint32_t afr[4][4], bfr[4][2], btmp[4];
            #pragma unroll
            for (int mb = 0; mb < 4; mb++) {
                if (TRA) ldsm4t(afr[mb], aB + (ks * 16 * SMK + mb * 16) * 2);
                else     ldsm4 (afr[mb], aB + (mb * 16 * SMJ + ks * 16) * 2);
            }
            #pragma unroll
            for (int h = 0; h < 2; h++) {
                if (TRB) ldsm4t(btmp, bB + (ks * 16 * SMK + h * 16) * 2);
                else     ldsm4 (btmp, bB + (h * 16 * SMJ + ks * 16) * 2);
                bfr[2 * h][0]     = btmp[0]; bfr[2 * h][1]     = btmp[1];
                bfr[2 * h + 1][0] = btmp[2]; bfr[2 * h + 1][1] = btmp[3];
            }
            #pragma unroll
            for (int mb = 0; mb < 4; mb++)
                #pragma unroll
                for (int nb = 0; nb < 4; nb++)
                    mma16816(acc[mb][nb], afr[mb], bfr[nb]);
        }
        sc = (sc == 2) ? 0 : sc + 1;
        sl = (sl == 2) ? 0 : sl + 1;
    }

    const float alpha = alpha_ptr ? *alpha_ptr : 1.0f;
    OUT* C = Cg + (long long)blockIdx.z * sC + (long long)blockIdx.y * 128 * ldc
           + (long long)blockIdx.x * 128;
    const int colbase = blockIdx.x * 128;
    #pragma unroll
    for (int mb = 0; mb < 4; mb++) {
        const int row = warp_m + mb * 16 + gid;
        #pragma unroll
        for (int nb = 0; nb < 4; nb++) {
            const int col = warp_n + nb * 8 + 2 * t4;
            float bx = 0.0f, by = 0.0f;
            if (bias) { bx = bias[colbase + col]; by = bias[colbase + col + 1]; }
            store2(&C[(long long)row * ldc + col],
                   acc[mb][nb][0] * alpha + bx, acc[mb][nb][1] * alpha + by);
            store2(&C[(long long)(row + 8) * ldc + col],
                   acc[mb][nb][2] * alpha + bx, acc[mb][nb][3] * alpha + by);
        }
    }
}

// ---------------------------------------------------------------------------
// sim GEMM with f16 accumulators: Am[b] = (vp[b] @ lp[b]^T) * scale, half out.
// CTA 128x256x32, 8 warps (2x4), warp tile 64x64. 3-stage, 2 CTA/SM.
// grid = (SEQ/256, SEQ/128, BATCH).
// ---------------------------------------------------------------------------
#define SIM_AH (128 * SMS)    // 5120 halves per A stage
#define SIM_BH (256 * SMS)    // 10240 halves per B stage
#define SIM_BYTES (3 * (SIM_AH + SIM_BH) * 2)   // 92160

__global__ __launch_bounds__(256, 2)
void sim_gemm_h16(const __half* __restrict__ vp, const __half* __restrict__ lp,
                  __half* __restrict__ Am, const float* __restrict__ alpha_ptr) {
    extern __shared__ char dynsm[];
    __half* Asm = reinterpret_cast<__half*>(dynsm);
    __half* Bsm = Asm + 3 * SIM_AH;

    const int tid  = threadIdx.x;
    const int wid  = tid >> 5;
    const int lane = tid & 31;
    const int gid  = lane >> 2;
    const int t4   = lane & 3;
    const int warp_m = (wid >> 2) * 64;    // 0,64
    const int warp_n = (wid & 3) * 64;     // 0,64,128,192

    const long long SD = (long long)SEQ * DIM;
    const __half* A = vp + (long long)blockIdx.z * SD + (long long)blockIdx.y * 128 * DIM;
    const __half* B = lp + (long long)blockIdx.z * SD + (long long)blockIdx.x * 256 * DIM;

    const int aoff = (warp_m + (lane & 7) + 8 * ((lane >> 3) & 1)) * SMS + 8 * (lane >> 4);
    const int boff = (warp_n + (lane & 7) + 8 * (lane >> 4)) * SMS + 8 * ((lane >> 3) & 1);
    const uint32_t aBase0 = smem_u32(&Asm[aoff]);
    const uint32_t bBase0 = smem_u32(&Bsm[boff]);

    uint32_t acc[4][8][2] = {};    // f16x2 accumulators
    const int KT = DIM >> 5;       // 24

    auto load_stage = [&](int st, int kt) {
        const int k0 = kt * 32;
        __half* As = Asm + st * SIM_AH;
        __half* Bs = Bsm + st * SIM_BH;
        #pragma unroll
        for (int i = 0; i < 2; i++) {              // A: 512 chunks
            int chunk = tid + i * 256;
            int row = chunk >> 2, c = (chunk & 3) * 8;
            cp16(&As[row * SMS + c], A + (long long)row * DIM + k0 + c);
        }
        #pragma unroll
        for (int i = 0; i < 4; i++) {              // B: 1024 chunks
            int chunk = tid + i * 256;
            int row = chunk >> 2, c = (chunk & 3) * 8;
            cp16(&Bs[row * SMS + c], B + (long long)row * DIM + k0 + c);
        }
        asm volatile("cp.async.commit_group;" ::: "memory");
    };

    load_stage(0, 0);
    load_stage(1, 1);

    int sc = 0, sl = 2;
    for (int kt = 0; kt < KT; kt++) {
        if (kt + 1 < KT) asm volatile("cp.async.wait_group 1;" ::: "memory");
        else             asm volatile("cp.async.wait_group 0;" ::: "memory");
        __syncthreads();

        if (kt + 2 < KT) load_stage(sl, kt + 2);

        const uint32_t aB = aBase0 + sc * SIM_AH * 2;
        const uint32_t bB = bBase0 + sc * SIM_BH * 2;
        #pragma unroll
        for (int ks = 0; ks < 2; ks++) {
            uint32_t afr[4][4], bfr[8][2], btmp[4];
            #pragma unroll
            for (int mb = 0; mb < 4; mb++)
                ldsm4(afr[mb], aB + (mb * 16 * SMS + ks * 16) * 2);
            #pragma unroll
            for (int h = 0; h < 4; h++) {
                ldsm4(btmp, bB + (h * 16 * SMS + ks * 16) * 2);
                bfr[2 * h][0]     = btmp[0]; bfr[2 * h][1]     = btmp[1];
                bfr[2 * h + 1][0] = btmp[2]; bfr[2 * h + 1][1] = btmp[3];
            }
            #pragma unroll
            for (int mb = 0; mb < 4; mb++)
                #pragma unroll
                for (int nb = 0; nb < 8; nb++)
                    mma16816h(acc[mb][nb], afr[mb], bfr[nb]);
        }
        sc = (sc == 2) ? 0 : sc + 1;
        sl = (sl == 2) ? 0 : sl + 1;
    }

    const float alpha = *alpha_ptr;
    __half* C = Am + (long long)blockIdx.z * SEQ * SEQ
              + (long long)blockIdx.y * 128 * SEQ + (long long)blockIdx.x * 256;
    #pragma unroll
    for (int mb = 0; mb < 4; mb++) {
        const int row = warp_m + mb * 16 + gid;
        #pragma unroll
        for (int nb = 0; nb < 8; nb++) {
            const int col = warp_n + nb * 8 + 2 * t4;
            float2 v0 = __half22float2(*reinterpret_cast<__half2*>(&acc[mb][nb][0]));
            float2 v1 = __half22float2(*reinterpret_cast<__half2*>(&acc[mb][nb][1]));
            store2(&C[(long long)row * SEQ + col], v0.x * alpha, v0.y * alpha);
            store2(&C[(long long)(row + 8) * SEQ + col], v1.x * alpha, v1.y * alpha);
        }
    }
}

// ---------------------------------------------------------------------------
// Merged aligned GEMM: role 0: comb[:,:768] = A @ vp ; role 1: comb[:,768:] = A^T @ lp
// ---------------------------------------------------------------------------
#define AHMAX (128 * SMJ)
#define ADG_BYTES (3 * (AHMAX + 64 * SMK) * 2)

__global__ __launch_bounds__(256, 2)
void aligned_dual_gemm(const __half* __restrict__ Amg, const __half* __restrict__ vp,
                       const __half* __restrict__ lp, __half* __restrict__ comb) {
    extern __shared__ char dynsm[];
    __half* Asm = reinterpret_cast<__half*>(dynsm);
    __half* Bsm = Asm + 3 * AHMAX;

    const int tid  = threadIdx.x;
    const int wid  = tid >> 5;
    const int lane = tid & 31;
    const int gid  = lane >> 2;
    const int t4   = lane & 3;
    const int warp_m = (wid >> 2) * 64;
    const int warp_n = (wid & 3) * 32;

    const int role = blockIdx.z & 1;
    const int bat  = blockIdx.z >> 1;
    const long long SS = (long long)SEQ * SEQ;
    const long long SD = (long long)SEQ * DIM;

    const __half* A = Amg + (long long)bat * SS
                    + (role ? (long long)blockIdx.y * 128
                            : (long long)blockIdx.y * 128 * SEQ);
    const __half* B = (role ? lp : vp) + (long long)bat * SD + (long long)blockIdx.x * 128;

    const int aoff = role
        ? ((lane & 7) + 8 * (lane >> 4)) * SMK + warp_m + 8 * ((lane >> 3) & 1)
        : (warp_m + (lane & 7) + 8 * ((lane >> 3) & 1)) * SMJ + 8 * (lane >> 4);
    const int boff = ((lane & 7) + 8 * ((lane >> 3) & 1)) * SMK + warp_n + 8 * (lane >> 4);
    const uint32_t aBase0 = smem_u32(&Asm[aoff]);
    const uint32_t bBase0 = smem_u32(&Bsm[boff]);

    float acc[4][4][4] = {};
    const int KT = SEQ >> 6;

    auto load_stage = [&](int st, int kt) {
        const int k0 = kt * 64;
        __half* As = Asm + st * AHMAX;
        __half* Bs = Bsm + st * (64 * SMK);
        #pragma unroll
        for (int i = 0; i < 4; i++) {
            int chunk = tid + i * 256;
            if (role == 0) {
                int row = chunk >> 3, c = (chunk & 7) * 8;
                cp16(&As[row * SMJ + c], A + (long long)row * SEQ + k0 + c);
            } else {
                int row = chunk >> 4, c = (chunk & 15) * 8;
                cp16(&As[row * SMK + c], A + (long long)(k0 + row) * SEQ + c);
            }
            {
                int row = chunk >> 4, c = (chunk & 15) * 8;
                cp16(&Bs[row * SMK + c], B + (long long)(k0 + row) * DIM + c);
            }
        }
        asm volatile("cp.async.commit_group;" ::: "memory");
    };

    load_stage(0, 0);
    load_stage(1, 1);

    int sc = 0, sl = 2;
    for (int kt = 0; kt < KT; kt++) {
        if (kt + 1 < KT) asm volatile("cp.async.wait_group 1;" ::: "memory");
        else             asm volatile("cp.async.wait_group 0;" ::: "memory");
        __syncthreads();

        if (kt + 2 < KT) load_stage(sl, kt + 2);

        const uint32_t aB = aBase0 + sc * AHMAX * 2;
        const uint32_t bB = bBase0 + sc * (64 * SMK) * 2;
        #pragma unroll
        for (int ks = 0; ks < 4; ks++) {
            uint32_t afr[4][4], bfr[4][2], btmp[4];
            #pragma unroll
            for (int mb = 0; mb < 4; mb++) {
                if (role) ldsm4t(afr[mb], aB + (ks * 16 * SMK + mb * 16) * 2);
                else      ldsm4 (afr[mb], aB + (mb * 16 * SMJ + ks * 16) * 2);
            }
            #pragma unroll
            for (int h = 0; h < 2; h++) {
                ldsm4t(btmp, bB + (ks * 16 * SMK + h * 16) * 2);
                bfr[2 * h][0]     = btmp[0]; bfr[2 * h][1]     = btmp[1];
                bfr[2 * h + 1][0] = btmp[2]; bfr[2 * h + 1][1] = btmp[3];
            }
            #pragma unroll
            for (int mb = 0; mb < 4; mb++)
                #pragma unroll
                for (int nb = 0; nb < 4; nb++)
                    mma16816(acc[mb][nb], afr[mb], bfr[nb]);
        }
        sc = (sc == 2) ? 0 : sc + 1;
        sl = (sl == 2) ? 0 : sl + 1;
    }

    __half* C = comb + (long long)bat * SEQ * 2 * DIM + role * DIM
              + (long long)blockIdx.y * 128 * (2 * DIM) + (long long)blockIdx.x * 128;
    #pragma unroll
    for (int mb = 0; mb < 4; mb++) {
        const int row = warp_m + mb * 16 + gid;
        #pragma unroll
        for (int nb = 0; nb < 4; nb++) {
            const int col = warp_n + nb * 8 + 2 * t4;
            store2(&C[(long long)row * (2 * DIM) + col], acc[mb][nb][0], acc[mb][nb][1]);
            store2(&C[(long long)(row + 8) * (2 * DIM) + col], acc[mb][nb][2], acc[mb][nb][3]);
        }
    }
}

// ---------------------------------------------------------------------------
// Reductions
// ---------------------------------------------------------------------------
__device__ __forceinline__ float blk_sum256(float v, float* ws, int tid) {
    #pragma unroll
    for (int o = 16; o > 0; o >>= 1) v += __shfl_xor_sync(0xFFFFFFFFu, v, o);
    if ((tid & 31) == 0) ws[tid >> 5] = v;
    __syncthreads();
    float t = ws[0];
    #pragma unroll
    for (int i = 1; i < 8; i++) t += ws[i];
    return t;
}

// ---------------------------------------------------------------------------
// Merged prep: claw partials | bias pack | weight f2h | input f2h
// ---------------------------------------------------------------------------
#define W4 (DIM * DIM / 4)
#define N4 (ROWS * DIM / 4)
#define PREP_BLOCKS (144 + 1 + (4 * W4 / 256) + (2 * N4 / 256))

__device__ __forceinline__ void f2h_quad(const float* in, __half* out, int j) {
    float4 v = reinterpret_cast<const float4*>(in)[j];
    __half2* o = reinterpret_cast<__half2*>(out);
    o[2 * j]     = __floats2half2_rn(v.x, v.y);
    o[2 * j + 1] = __floats2half2_rn(v.z, v.w);
}

__global__ void prep_kernel(const float* __restrict__ claw,
                            const float* __restrict__ vb, const float* __restrict__ lb,
                            const float* __restrict__ vW, const float* __restrict__ lW,
                            const float* __restrict__ oW,
                            const float* __restrict__ vis, const float* __restrict__ lang) {
    __shared__ float ws[8];
    const int bx = blockIdx.x, tid = threadIdx.x;
    if (bx < 144) {
        const float* p = claw + (long long)bx * 4096;
        float s = 0.0f;
        #pragma unroll
        for (int i = 0; i < 4; i++) {
            float4 v = reinterpret_cast<const float4*>(p)[tid + i * 256];
            s += v.x + v.y + v.z + v.w;
        }
        s = blk_sum256(s, ws, tid);
        if (tid == 0) g_part[bx] = s;
    } else if (bx == 144) {
        #pragma unroll
        for (int i = 0; i < 6; i++) {
            int j = tid + i * 256;
            g_pb[j] = (j < DIM) ? vb[j] : lb[j - DIM];
        }
    } else if (bx < 145 + 4 * W4 / 256) {
        int j = (bx - 145) * 256 + tid;
        if (j < W4)            f2h_quad(vW, g_WH, j);
        else if (j < 2 * W4)   f2h_quad(lW, g_WH + DIM * DIM, j - W4);
        else                   f2h_quad(oW, g_oWH, j - 2 * W4);
    } else {
        int j = (bx - (145 + 4 * W4 / 256)) * 256 + tid;
        if (j < N4) f2h_quad(vis, g_inH, j);
        else        f2h_quad(lang, g_inH + (long long)ROWS * DIM, j - N4);
    }
}

// ---------------------------------------------------------------------------
// Warp-per-row LayerNorm (+ReLU): 8 rows per 256-thread block.
// ---------------------------------------------------------------------------
__device__ __forceinline__ void ln_warp_row_h(const __half* __restrict__ xrow,
                                              __half* __restrict__ yrow,
                                              const float* __restrict__ g,
                                              const float* __restrict__ beta, int lane) {
    const int4* xv = reinterpret_cast<const int4*>(xrow);
    int4 raw[3];
    float v[24];
    #pragma unroll
    for (int i = 0; i < 3; i++) raw[i] = xv[lane + 32 * i];
    #pragma unroll
    for (int i = 0; i < 3; i++) {
        const __half2* h = reinterpret_cast<const __half2*>(&raw[i]);
        #pragma unroll
        for (int j = 0; j < 4; j++) {
            float2 f = __half22float2(h[j]);
            v[i * 8 + 2 * j] = f.x; v[i * 8 + 2 * j + 1] = f.y;
        }
    }
    float s = 0.0f, s2 = 0.0f;
    #pragma unroll
    for (int k = 0; k < 24; k++) { s += v[k]; s2 += v[k] * v[k]; }
    #pragma unroll
    for (int o = 16; o > 0; o >>= 1) {
        s  += __shfl_xor_sync(0xFFFFFFFFu, s,  o);
        s2 += __shfl_xor_sync(0xFFFFFFFFu, s2, o);
    }
    const float m  = s * (1.0f / DIM);
    const float rs = rsqrtf(s2 * (1.0f / DIM) - m * m + 1e-5f);
    const float4* g4 = reinterpret_cast<const float4*>(g);
    const float4* b4 = reinterpret_cast<const float4*>(beta);
    int4* yv = reinterpret_cast<int4*>(yrow);
    #pragma unroll
    for (int i = 0; i < 3; i++) {
        int ci = (lane + 32 * i) * 2;
        float4 G0 = g4[ci], G1 = g4[ci + 1], B0 = b4[ci], B1 = b4[ci + 1];
        int4 o;
        __half2* oh = reinterpret_cast<__half2*>(&o);
        oh[0] = __floats2half2_rn(fmaxf(0.0f, (v[i*8+0]-m)*rs*G0.x + B0.x),
                                  fmaxf(0.0f, (v[i*8+1]-m)*rs*G0.y + B0.y));
        oh[1] = __floats2half2_rn(fmaxf(0.0f, (v[i*8+2]-m)*rs*G0.z + B0.z),
                                  fmaxf(0.0f, (v[i*8+3]-m)*rs*G0.w + B0.w));
        oh[2] = __floats2half2_rn(fmaxf(0.0f, (v[i*8+4]-m)*rs*G1.x + B1.x),
                                  fmaxf(0.0f, (v[i*8+5]-m)*rs*G1.y + B1.y));
        oh[3] = __floats2half2_rn(fmaxf(0.0f, (v[i*8+6]-m)*rs*G1.z + B1.z),
                                  fmaxf(0.0f, (v[i*8+7]-m)*rs*G1.w + B1.w));
        yv[lane + 32 * i] = o;
    }
}

__device__ __forceinline__ void ln_warp_row_f(const __half* __restrict__ xrow,
                                              float* __restrict__ yrow,
                                              const float* __restrict__ g,
                                              const float* __restrict__ beta, int lane) {
    const int4* xv = reinterpret_cast<const int4*>(xrow);
    int4 raw[3];
    float v[24];
    #pragma unroll
    for (int i = 0; i < 3; i++) raw[i] = xv[lane + 32 * i];
    #pragma unroll
    for (int i = 0; i < 3; i++) {
        const __half2* h = reinterpret_cast<const __half2*>(&raw[i]);
        #pragma unroll
        for (int j = 0; j < 4; j++) {
            float2 f = __half22float2(h[j]);
            v[i * 8 + 2 * j] = f.x; v[i * 8 + 2 * j + 1] = f.y;
        }
    }
    float s = 0.0f, s2 = 0.0f;
    #pragma unroll
    for (int k = 0; k < 24; k++) { s += v[k]; s2 += v[k] * v[k]; }
    #pragma unroll
    for (int o = 16; o > 0; o >>= 1) {
        s  += __shfl_xor_sync(0xFFFFFFFFu, s,  o);
        s2 += __shfl_xor_sync(0xFFFFFFFFu, s2, o);
    }
    const float m  = s * (1.0f / DIM);
    const float rs = rsqrtf(s2 * (1.0f / DIM) - m * m + 1e-5f);
    const float4* g4 = reinterpret_cast<const float4*>(g);
    const float4* b4 = reinterpret_cast<const float4*>(beta);
    float4* yv = reinterpret_cast<float4*>(yrow);
    #pragma unroll
    for (int i = 0; i < 3; i++) {
        int ci = (lane + 32 * i) * 2;
        float4 G0 = g4[ci], G1 = g4[ci + 1], B0 = b4[ci], B1 = b4[ci + 1];
        float4 o0, o1;
        o0.x = fmaxf(0.0f, (v[i*8+0]-m)*rs*G0.x + B0.x);
        o0.y = fmaxf(0.0f, (v[i*8+1]-m)*rs*G0.y + B0.y);
        o0.z = fmaxf(0.0f, (v[i*8+2]-m)*rs*G0.z + B0.z);
        o0.w = fmaxf(0.0f, (v[i*8+3]-m)*rs*G0.w + B0.w);
        o1.x = fmaxf(0.0f, (v[i*8+4]-m)*rs*G1.x + B1.x);
        o1.y = fmaxf(0.0f, (v[i*8+5]-m)*rs*G1.y + B1.y);
        o1.z = fmaxf(0.0f, (v[i*8+6]-m)*rs*G1.z + B1.z);
        o1.w = fmaxf(0.0f, (v[i*8+7]-m)*rs*G1.w + B1.w);
        yv[ci]     = o0;
        yv[ci + 1] = o1;
    }
}

#define LN_DUAL_BLOCKS (2 * ROWS / 8 + 1)
__global__ void ln_relu_dual_kernel(const __half* __restrict__ X0, __half* __restrict__ Y0,
                                    const float* __restrict__ g0, const float* __restrict__ b0,
                                    const __half* __restrict__ X1, __half* __restrict__ Y1,
                                    const float* __restrict__ g1, const float* __restrict__ b1) {
    if (blockIdx.x == LN_DUAL_BLOCKS - 1) {
        __shared__ float ws[8];
        float s = (threadIdx.x < 144) ? g_part[threadIdx.x] : 0.0f;
        s = blk_sum256(s, ws, threadIdx.x);
        if (threadIdx.x == 0) g_scale = (s / (float)(DIM * DIM)) * TEMP_INV;
        return;
    }
    const int lane = threadIdx.x & 31;
    long long r = (long long)blockIdx.x * 8 + (threadIdx.x >> 5);
    if (r < ROWS) ln_warp_row_h(X0 + r * DIM, Y0 + r * DIM, g0, b0, lane);
    else {
        r -= ROWS;
        ln_warp_row_h(X1 + r * DIM, Y1 + r * DIM, g1, b1, lane);
    }
}

__global__ void ln_relu_f_kernel(const __half* __restrict__ X, float* __restrict__ Y,
                                 const float* __restrict__ g, const float* __restrict__ beta) {
    const int lane = threadIdx.x & 31;
    long long r = (long long)blockIdx.x * 8 + (threadIdx.x >> 5);
    ln_warp_row_f(X + r * DIM, Y + r * DIM, g, beta, lane);
}

// ---------------------------------------------------------------------------
// Warp-per-row softmax over 2048, half, in place. 8 rows per block, 64 vals/lane.
// ---------------------------------------------------------------------------
__global__ void softmax_h_kernel(__half* __restrict__ X) {
    const int lane = threadIdx.x & 31;
    long long r = (long long)blockIdx.x * 8 + (threadIdx.x >> 5);
    int4* xv = reinterpret_cast<int4*>(X + r * SEQ);

    int4 raw[8];
    float v[64];
    #pragma unroll
    for (int i = 0; i < 8; i++) raw[i] = xv[lane + 32 * i];
    #pragma unroll
    for (int i = 0; i < 8; i++) {
        const __half2* h = reinterpret_cast<const __half2*>(&raw[i]);
        #pragma unroll
        for (int j = 0; j < 4; j++) {
            float2 f = __half22float2(h[j]);
            v[i * 8 + 2 * j] = f.x; v[i * 8 + 2 * j + 1] = f.y;
        }
    }
    float mx = v[0];
    #pragma unroll
    for (int k = 1; k < 64; k++) mx = fmaxf(mx, v[k]);
    #pragma unroll
    for (int o = 16; o > 0; o >>= 1) mx = fmaxf(mx, __shfl_xor_sync(0xFFFFFFFFu, mx, o));

    float sum = 0.0f;
    #pragma unroll
    for (int k = 0; k < 64; k++) { v[k] = __expf(v[k] - mx); sum += v[k]; }
    #pragma unroll
    for (int o = 16; o > 0; o >>= 1) sum += __shfl_xor_sync(0xFFFFFFFFu, sum, o);
    const float inv = 1.0f / sum;

    #pragma unroll
    for (int i = 0; i < 8; i++) {
        int4 o;
        __half2* oh = reinterpret_cast<__half2*>(&o);
        #pragma unroll
        for (int j = 0; j < 4; j++)
            oh[j] = __floats2half2_rn(v[i * 8 + 2 * j] * inv, v[i * 8 + 2 * j + 1] * inv);
        xv[lane + 32 * i] = o;
    }
}

// ---------------------------------------------------------------------------
// Launch
// ---------------------------------------------------------------------------
extern "C" void kernel_launch(void* const* d_in, const int* in_sizes, int n_in,
                              void* d_out, int out_size) {
    const float* vis   = (const float*)d_in[0];
    const float* lang  = (const float*)d_in[1];
    const float* vW    = (const float*)d_in[2];
    const float* vb    = (const float*)d_in[3];
    const float* vg    = (const float*)d_in[4];
    const float* vbeta = (const float*)d_in[5];
    const float* lW    = (const float*)d_in[6];
    const float* lb    = (const float*)d_in[7];
    const float* lg    = (const float*)d_in[8];
    const float* lbeta = (const float*)d_in[9];
    const float* claw  = (const float*)d_in[10];
    const float* oW    = (const float*)d_in[11];
    const float* ob    = (const float*)d_in[12];
    const float* og    = (const float*)d_in[13];
    const float* obeta = (const float*)d_in[14];
    float* out = (float*)d_out;

    float  *scale, *pb;
    __half *inH, *vpH, *lpH, *AmH, *combH, *WH, *oWH;
    cudaGetSymbolAddress((void**)&inH,   g_inH);
    cudaGetSymbolAddress((void**)&vpH,   g_vpH);
    cudaGetSymbolAddress((void**)&lpH,   g_lpH);
    cudaGetSymbolAddress((void**)&AmH,   g_AmH);
    cudaGetSymbolAddress((void**)&combH, g_combH);
    cudaGetSymbolAddress((void**)&WH,    g_WH);
    cudaGetSymbolAddress((void**)&oWH,   g_oWH);
    cudaGetSymbolAddress((void**)&scale, g_scale);
    cudaGetSymbolAddress((void**)&pb,    g_pb);

    __half* tmpH0 = combH;
    __half* outH  = inH;

    const long long RD = (long long)ROWS * DIM;

    constexpr int SM01 = GemmSmem<0, 1>::BYTES;
    cudaFuncSetAttribute(h_gemm<0, 1, __half>, cudaFuncAttributeMaxDynamicSharedMemorySize, SM01);
    cudaFuncSetAttribute(sim_gemm_h16, cudaFuncAttributeMaxDynamicSharedMemorySize, SIM_BYTES);
    cudaFuncSetAttribute(aligned_dual_gemm, cudaFuncAttributeMaxDynamicSharedMemorySize, ADG_BYTES);

    prep_kernel<<<PREP_BLOCKS, 256>>>(claw, vb, lb, vW, lW, oW, vis, lang);

    // dual proj GEMM: z=0 vis/vW/vb, z=1 lang/lW/lb
    h_gemm<0, 1, __half><<<dim3(DIM / 128, ROWS / 128, 2), 256, SM01>>>(
        inH, WH, tmpH0, DIM, DIM, DIM, DIM,
        RD, (long long)DIM * DIM, RD, DIM, nullptr, pb);

    // dual LN + ReLU -> vpH, lpH (warp per row) + claw finalize
    ln_relu_dual_kernel<<<LN_DUAL_BLOCKS, 256>>>(tmpH0, vpH, vg, vbeta,
                                                 tmpH0 + RD, lpH, lg, lbeta);

    // sim = (vp @ lp^T) * scale -> half (f16-acc 64x64 warp tiles)
    sim_gemm_h16<<<dim3(SEQ / 256, SEQ / 128, BATCH), 256, SIM_BYTES>>>(
        vpH, lpH, AmH, scale);

    softmax_h_kernel<<<BATCH * SEQ / 8, 256>>>(AmH);

    // merged aligned GEMMs
    aligned_dual_gemm<<<dim3(DIM / 128, SEQ / 128, 2 * BATCH), 256, ADG_BYTES>>>(
        AmH, vpH, lpH, combH);

    // out_pre = comb @ oW + ob -> half (inH scratch)
    h_gemm<0, 1, __half><<<dim3(DIM / 128, ROWS / 128, 1), 256, SM01>>>(
        combH, oWH, outH, 2 * DIM, DIM, DIM, 2 * DIM, 0, 0, 0, 0, nullptr, ob);

    // final LN + ReLU -> f32 out (warp per row)
    ln_relu_f_kernel<<<ROWS / 8, 256>>>(outH, out, og, obeta);
}